// round 4
// baseline (speedup 1.0000x reference)
#include <cuda_runtime.h>
#include <cuda_bf16.h>
#include <cstdint>

// ---------------------------------------------------------------------------
// Problem constants
// ---------------------------------------------------------------------------
static constexpr int BATCH = 8192;
static constexpr int D     = 2048;           // input feature dim (K of GEMM)
static constexpr int DK    = 1024;           // projection dim
static constexpr int ROWS  = BATCH * 3;      // 24576 rows per tensor
static constexpr int GM    = ROWS * 2;       // 49152 (img rows then text rows)
static constexpr int GN    = 2 * DK;         // 2048  (Q cols then K cols)
static constexpr int GK    = D;              // 2048
static constexpr float NORM_FACT = 0.03125f; // 1/sqrt(1024)

// M partition: tensor-core rows vs fp32-FFMA rows
static constexpr int TC_ROWS = 32768;        // rows [0, 32768): tc path (bf16 3-term)
static constexpr int FF_ROWS = 16384;        // rows [32768, 49152): ffma path (fp32)
static constexpr int E_ROWS  = 64;           // ffma rows per CTA

// GEMM tiling
static constexpr int TILE_M = 128;           // tc rows per CTA
static constexpr int TILE_N = 128;
static constexpr int BK     = 64;            // k elems per chunk
static constexpr int NCHUNK = GK / BK;       // 32
static constexpr int NSTAGE = 2;

// SMEM stage layout (bytes)
static constexpr int OP_TILE   = 128 * 128;              // 16 KB (bf16 tile, 128 rows x 128B)
static constexpr int AF_OFF    = 4 * OP_TILE;            // 65536
static constexpr int AF_BYTES  = BK * E_ROWS * 4;        // 16 KB  Af[ks][64 rows] f32
static constexpr int BF_OFF    = AF_OFF + AF_BYTES;      // 81920
static constexpr int BF_BYTES  = BK * TILE_N * 4;        // 32 KB  Bf[ks][128 n] f32
static constexpr int STAGE_BYTES = BF_OFF + BF_BYTES;    // 114688
static constexpr int SMEM_TOTAL  = NSTAGE * STAGE_BYTES; // 229376 (224 KB)

static constexpr int NTHREADS = 384;         // 256 tc + 128 ffma

// ---------------------------------------------------------------------------
// Device scratch
// ---------------------------------------------------------------------------
__device__ __align__(16) __nv_bfloat16 g_Ah[(size_t)TC_ROWS * GK];
__device__ __align__(16) __nv_bfloat16 g_Al[(size_t)TC_ROWS * GK];
__device__ __align__(16) __nv_bfloat16 g_Bh[(size_t)GN * GK];
__device__ __align__(16) __nv_bfloat16 g_Bl[(size_t)GN * GK];
__device__ __align__(16) float         g_AfT[(size_t)GK * FF_ROWS];  // [k][row]
__device__ __align__(16) float         g_BfT[(size_t)GK * GN];       // [k][n]
__device__ __align__(16) float         g_QK[(size_t)GM * GN];

// ---------------------------------------------------------------------------
// PTX helpers (portable sm_80-era ISA)
// ---------------------------------------------------------------------------
__device__ __forceinline__ uint32_t smem_u32(const void* p) {
    uint32_t a;
    asm("{ .reg .u64 t; cvta.to.shared.u64 t, %1; cvt.u32.u64 %0, t; }" : "=r"(a) : "l"(p));
    return a;
}
__device__ __forceinline__ void cp16(uint32_t dst, const void* src) {
    asm volatile("cp.async.cg.shared.global [%0], [%1], 16;" :: "r"(dst), "l"(src));
}
__device__ __forceinline__ void cp_commit() {
    asm volatile("cp.async.commit_group;" ::: "memory");
}
template <int N>
__device__ __forceinline__ void cp_wait() {
    asm volatile("cp.async.wait_group %0;" :: "n"(N) : "memory");
}
__device__ __forceinline__ void ldmx4(uint32_t* r, uint32_t addr) {
    asm volatile("ldmatrix.sync.aligned.m8n8.x4.shared.b16 {%0,%1,%2,%3}, [%4];"
                 : "=r"(r[0]), "=r"(r[1]), "=r"(r[2]), "=r"(r[3]) : "r"(addr));
}
__device__ __forceinline__ void mma_bf16(float* c, const uint32_t* a, uint32_t b0, uint32_t b1) {
    asm volatile(
        "mma.sync.aligned.m16n8k16.row.col.f32.bf16.bf16.f32 "
        "{%0,%1,%2,%3}, {%4,%5,%6,%7}, {%8,%9}, {%0,%1,%2,%3};"
        : "+f"(c[0]), "+f"(c[1]), "+f"(c[2]), "+f"(c[3])
        : "r"(a[0]), "r"(a[1]), "r"(a[2]), "r"(a[3]), "r"(b0), "r"(b1));
}

// ---------------------------------------------------------------------------
// Convert kernels: fp32 -> bf16 hi + lo residual (tc rows / weights only)
// ---------------------------------------------------------------------------
__global__ void convertA_kernel(const float* __restrict__ img, const float* __restrict__ text) {
    const size_t i = (size_t)blockIdx.x * blockDim.x + threadIdx.x;     // float4 index
    const size_t half = (size_t)ROWS * GK / 4;                          // img count
    // covers rows [0, TC_ROWS): all img + first 8192 text rows
    const float4 v = (i < half) ? ((const float4*)img)[i] : ((const float4*)text)[i - half];
    __nv_bfloat16 h0 = __float2bfloat16_rn(v.x), h1 = __float2bfloat16_rn(v.y);
    __nv_bfloat16 h2 = __float2bfloat16_rn(v.z), h3 = __float2bfloat16_rn(v.w);
    __nv_bfloat162* ah = (__nv_bfloat162*)g_Ah;
    __nv_bfloat162* al = (__nv_bfloat162*)g_Al;
    ah[2 * i]     = __nv_bfloat162(h0, h1);
    ah[2 * i + 1] = __nv_bfloat162(h2, h3);
    al[2 * i]     = __nv_bfloat162(__float2bfloat16_rn(v.x - __bfloat162float(h0)),
                                   __float2bfloat16_rn(v.y - __bfloat162float(h1)));
    al[2 * i + 1] = __nv_bfloat162(__float2bfloat16_rn(v.z - __bfloat162float(h2)),
                                   __float2bfloat16_rn(v.w - __bfloat162float(h3)));
}

__global__ void convertB_kernel(const float* __restrict__ Wq, const float* __restrict__ Wk) {
    const size_t i = (size_t)blockIdx.x * blockDim.x + threadIdx.x;     // float4 index
    const size_t half = (size_t)DK * GK / 4;
    const float4 v = (i < half) ? ((const float4*)Wq)[i] : ((const float4*)Wk)[i - half];
    __nv_bfloat16 h0 = __float2bfloat16_rn(v.x), h1 = __float2bfloat16_rn(v.y);
    __nv_bfloat16 h2 = __float2bfloat16_rn(v.z), h3 = __float2bfloat16_rn(v.w);
    __nv_bfloat162* bh = (__nv_bfloat162*)g_Bh;
    __nv_bfloat162* bl = (__nv_bfloat162*)g_Bl;
    bh[2 * i]     = __nv_bfloat162(h0, h1);
    bh[2 * i + 1] = __nv_bfloat162(h2, h3);
    bl[2 * i]     = __nv_bfloat162(__float2bfloat16_rn(v.x - __bfloat162float(h0)),
                                   __float2bfloat16_rn(v.y - __bfloat162float(h1)));
    bl[2 * i + 1] = __nv_bfloat162(__float2bfloat16_rn(v.z - __bfloat162float(h2)),
                                   __float2bfloat16_rn(v.w - __bfloat162float(h3)));
}

// ---------------------------------------------------------------------------
// Transpose kernels: build k-major fp32 copies for the FFMA path
// ---------------------------------------------------------------------------
__global__ void transA_kernel(const float* __restrict__ text) {
    __shared__ float t[32][33];
    const int k0 = blockIdx.x * 32;
    const int r0 = blockIdx.y * 32;
    // ffma rows are text rows [8192, 24576)
    for (int i = threadIdx.y; i < 32; i += 8)
        t[i][threadIdx.x] = text[(size_t)(8192 + r0 + i) * D + k0 + threadIdx.x];
    __syncthreads();
    for (int i = threadIdx.y; i < 32; i += 8)
        g_AfT[(size_t)(k0 + i) * FF_ROWS + r0 + threadIdx.x] = t[threadIdx.x][i];
}

__global__ void transB_kernel(const float* __restrict__ Wq, const float* __restrict__ Wk) {
    __shared__ float t[32][33];
    const int k0 = blockIdx.x * 32;
    const int n0 = blockIdx.y * 32;
    const float* W = (n0 < DK) ? Wq : Wk;
    const int nb = (n0 < DK) ? n0 : (n0 - DK);
    for (int i = threadIdx.y; i < 32; i += 8)
        t[i][threadIdx.x] = W[(size_t)(nb + i) * D + k0 + threadIdx.x];
    __syncthreads();
    for (int i = threadIdx.y; i < 32; i += 8)
        g_BfT[(size_t)(k0 + i) * GN + n0 + threadIdx.x] = t[threadIdx.x][i];
}

// ---------------------------------------------------------------------------
// Hybrid GEMM: 384 threads/CTA.
//   tid <  256: tensor-core path, 128x128 tile, bf16 3-term (hh+hl+lh)
//   tid >= 256: FFMA path, 64x128 tile in pure fp32 from k-major copies
// 2-stage cp.async pipeline shared by both roles.
// ---------------------------------------------------------------------------
__global__ void __launch_bounds__(NTHREADS, 1) gemm_hybrid_kernel(
    const float* __restrict__ bq, const float* __restrict__ bk)
{
    extern __shared__ char smem[];
    const uint32_t sbase = smem_u32(smem);
    const int tid  = threadIdx.x;
    const int warp = tid >> 5;
    const int lane = tid & 31;

    const int bn = blockIdx.x * TILE_N;
    const int by = blockIdx.y;
    const int bm = by * TILE_M;          // tc rows [bm, bm+128) in [0, TC_ROWS)

    const bool tc_role = (tid < 256);

    // ======================= load geometry =======================
    // tc loaders (tid < 256): Ah/Al/Bh/Bl, 16 cp16 each
    uint32_t swoff[4];
    const __nv_bfloat16 *gAh = nullptr, *gAl = nullptr, *gBh = nullptr, *gBl = nullptr;
    if (tc_role) {
        const int lr  = tid >> 1;          // 0..127
        const int lc0 = (tid & 1) * 4;     // 0 or 4
        gAh = g_Ah + (size_t)(bm + lr) * GK + lc0 * 8;
        gAl = g_Al + (size_t)(bm + lr) * GK + lc0 * 8;
        gBh = g_Bh + (size_t)(bn + lr) * GK + lc0 * 8;
        gBl = g_Bl + (size_t)(bn + lr) * GK + lc0 * 8;
        #pragma unroll
        for (int i = 0; i < 4; i++)
            swoff[i] = (uint32_t)(lr * 128 + (((lc0 + i) ^ (lr & 7)) * 16));
    }
    // ffma loaders (tid2 = tid-256): Af (8 cp16) + Bf (16 cp16)
    const int tid2 = tid - 256;            // 0..127 for ffma role
    const int ffr0 = by * E_ROWS;          // row base inside AfT space

    auto load_stage = [&](int c, int s) {
        const uint32_t st = sbase + s * STAGE_BYTES;
        if (tc_role) {
            const size_t kof = (size_t)c * BK;
            #pragma unroll
            for (int i = 0; i < 4; i++) {
                cp16(st +               swoff[i], gAh + kof + i * 8);
                cp16(st +     OP_TILE + swoff[i], gAl + kof + i * 8);
                cp16(st + 2 * OP_TILE + swoff[i], gBh + kof + i * 8);
                cp16(st + 3 * OP_TILE + swoff[i], gBl + kof + i * 8);
            }
        } else {
            // Af[ks][64 rows] f32: 1024 x 16B units
            #pragma unroll
            for (int i = 0; i < 8; i++) {
                const int u  = tid2 + 128 * i;
                const int ks = u >> 4, seg = u & 15;
                cp16(st + AF_OFF + u * 16,
                     g_AfT + (size_t)(c * BK + ks) * FF_ROWS + ffr0 + seg * 4);
            }
            // Bf[ks][128 n] f32: 2048 x 16B units
            #pragma unroll
            for (int i = 0; i < 16; i++) {
                const int u  = tid2 + 128 * i;
                const int ks = u >> 5, seg = u & 31;
                cp16(st + BF_OFF + u * 16,
                     g_BfT + (size_t)(c * BK + ks) * GN + bn + seg * 4);
            }
        }
        cp_commit();
    };

    // prologue
    load_stage(0, 0);
    load_stage(1, 1);

    // ======================= compute state =======================
    // tc role
    const int wm = warp & 1;
    const int wn = warp >> 1;              // 0..3 for warps 0..7
    uint32_t swz[4];
    uint32_t aWarp = 0, bWarp = 0;
    float acc_tc[4][4][4];
    // ffma role
    const int fty = tid2 >> 3;             // 0..15 -> 4 rows each
    const int ftx = tid2 & 7;              // 0..7  -> cols j*32 + ftx*4
    float acc_ff[4][16];

    if (tc_role) {
        const int lrow = lane & 15;
        const int lsel = lane >> 4;
        #pragma unroll
        for (int ks = 0; ks < 4; ks++)
            swz[ks] = (uint32_t)(lrow * 128 + (((ks * 2 + lsel) ^ (lrow & 7)) * 16));
        aWarp = sbase + (uint32_t)(wm * 64) * 128;
        bWarp = sbase + 2 * OP_TILE + (uint32_t)(wn * 32) * 128;
        #pragma unroll
        for (int i = 0; i < 4; i++)
            #pragma unroll
            for (int j = 0; j < 4; j++)
                #pragma unroll
                for (int k = 0; k < 4; k++) acc_tc[i][j][k] = 0.0f;
    } else {
        #pragma unroll
        for (int i = 0; i < 4; i++)
            #pragma unroll
            for (int j = 0; j < 16; j++) acc_ff[i][j] = 0.0f;
    }

    // ======================= main loop =======================
    for (int c = 0; c < NCHUNK; c++) {
        const int s = c & 1;
        cp_wait<1>();
        __syncthreads();

        if (tc_role) {
            const uint32_t aS = aWarp + s * STAGE_BYTES;
            const uint32_t bS = bWarp + s * STAGE_BYTES;
            #pragma unroll
            for (int ks = 0; ks < 4; ks++) {
                uint32_t ah[4][4], al[4][4], bh[2][4], bl[2][4];
                #pragma unroll
                for (int mf = 0; mf < 4; mf++) {
                    ldmx4(ah[mf], aS + mf * 2048 + swz[ks]);
                    ldmx4(al[mf], aS + OP_TILE + mf * 2048 + swz[ks]);
                }
                #pragma unroll
                for (int nf2 = 0; nf2 < 2; nf2++) {
                    ldmx4(bh[nf2], bS + nf2 * 2048 + swz[ks]);
                    ldmx4(bl[nf2], bS + OP_TILE + nf2 * 2048 + swz[ks]);
                }
                #pragma unroll
                for (int mf = 0; mf < 4; mf++) {
                    #pragma unroll
                    for (int nf = 0; nf < 4; nf++) {
                        const int nf2 = nf >> 1, sub = nf & 1;
                        mma_bf16(acc_tc[mf][nf], ah[mf], bh[nf2][sub], bh[nf2][sub + 2]);
                        mma_bf16(acc_tc[mf][nf], ah[mf], bl[nf2][sub], bl[nf2][sub + 2]);
                        mma_bf16(acc_tc[mf][nf], al[mf], bh[nf2][sub], bh[nf2][sub + 2]);
                    }
                }
            }
        } else {
            const char* af = smem + s * STAGE_BYTES + AF_OFF;
            const char* bf = smem + s * STAGE_BYTES + BF_OFF;
            #pragma unroll 4
            for (int ks = 0; ks < BK; ks++) {
                const float4 a = *(const float4*)(af + ks * (E_ROWS * 4) + fty * 16);
                float4 b[4];
                #pragma unroll
                for (int j = 0; j < 4; j++)
                    b[j] = *(const float4*)(bf + ks * (TILE_N * 4) + (j * 32 + ftx * 4) * 4);
                const float ar[4] = {a.x, a.y, a.z, a.w};
                #pragma unroll
                for (int i = 0; i < 4; i++) {
                    #pragma unroll
                    for (int j = 0; j < 4; j++) {
                        acc_ff[i][j * 4 + 0] += ar[i] * b[j].x;
                        acc_ff[i][j * 4 + 1] += ar[i] * b[j].y;
                        acc_ff[i][j * 4 + 2] += ar[i] * b[j].z;
                        acc_ff[i][j * 4 + 3] += ar[i] * b[j].w;
                    }
                }
            }
        }

        __syncthreads();   // everyone done reading stage s before overwrite
        if (c + NSTAGE < NCHUNK) load_stage(c + NSTAGE, s);
        else                     cp_commit();   // keep group counts uniform
    }

    // ======================= epilogue =======================
    const bool isQ = (bn < DK);
    const float* bias = isQ ? bq : bk;
    const int bcol0 = isQ ? bn : (bn - DK);

    if (tc_role) {
        const int trow = lane >> 2;
        const int tcol = (lane & 3) * 2;
        #pragma unroll
        for (int mf = 0; mf < 4; mf++) {
            const int r0 = bm + wm * 64 + mf * 16 + trow;
            #pragma unroll
            for (int nf = 0; nf < 4; nf++) {
                const int coln = wn * 32 + nf * 8 + tcol;
                const float2 bv = *(const float2*)(bias + bcol0 + coln);
                float2 v0, v1;
                v0.x = acc_tc[mf][nf][0] + bv.x;
                v0.y = acc_tc[mf][nf][1] + bv.y;
                v1.x = acc_tc[mf][nf][2] + bv.x;
                v1.y = acc_tc[mf][nf][3] + bv.y;
                *(float2*)&g_QK[(size_t)r0 * GN + bn + coln]       = v0;
                *(float2*)&g_QK[(size_t)(r0 + 8) * GN + bn + coln] = v1;
            }
        }
    } else {
        #pragma unroll
        for (int i = 0; i < 4; i++) {
            const int row = TC_ROWS + by * E_ROWS + fty * 4 + i;
            #pragma unroll
            for (int j = 0; j < 4; j++) {
                const int coln = j * 32 + ftx * 4;
                const float4 bv = *(const float4*)(bias + bcol0 + coln);
                float4 v;
                v.x = acc_ff[i][j * 4 + 0] + bv.x;
                v.y = acc_ff[i][j * 4 + 1] + bv.y;
                v.z = acc_ff[i][j * 4 + 2] + bv.z;
                v.w = acc_ff[i][j * 4 + 3] + bv.w;
                *(float4*)&g_QK[(size_t)row * GN + bn + coln] = v;
            }
        }
    }
}

// ---------------------------------------------------------------------------
// Kernel: per-batch attention algebra + output epilogue
// ---------------------------------------------------------------------------
__global__ void __launch_bounds__(256) attn_epilogue_kernel(
    const float* __restrict__ img,
    const float* __restrict__ text,
    const float* __restrict__ Wj,
    const float* __restrict__ bj,
    const float* __restrict__ Wbil,
    float* __restrict__ out)
{
    const int b    = blockIdx.x;
    const int tid  = threadIdx.x;
    const int warp = tid >> 5;
    const int lane = tid & 31;

    __shared__ float logits[3][3][3];
    __shared__ float attnI[3][3];
    __shared__ float attnT[3][3];

    for (int idx = warp; idx < 27; idx += 8) {
        const int map = idx / 9;
        const int r   = idx % 9;
        const int q   = r / 3;
        const int s   = r % 3;

        const size_t mi_q = (size_t)(b * 3 + q) * GN;
        const size_t mi_s = (size_t)(b * 3 + s) * GN;
        const size_t mt_q = (size_t)(ROWS + b * 3 + q) * GN;
        const size_t mt_s = (size_t)(ROWS + b * 3 + s) * GN;

        const float* a;
        const float* v;
        if (map == 0)      { a = g_QK + mi_q; v = g_QK + mt_s + DK; }
        else if (map == 1) { a = g_QK + mi_q; v = g_QK + mi_s + DK; }
        else               { a = g_QK + mt_q; v = g_QK + mt_s + DK; }

        float sum = 0.0f;
        for (int t = lane; t < DK; t += 32)
            sum += a[t] * v[t];
        #pragma unroll
        for (int off = 16; off > 0; off >>= 1)
            sum += __shfl_xor_sync(0xFFFFFFFFu, sum, off);
        if (lane == 0) logits[map][q][s] = sum;
    }
    __syncthreads();

    if (tid == 0) {
        float p[3][3][3];
        #pragma unroll
        for (int map = 0; map < 3; map++) {
            #pragma unroll
            for (int q = 0; q < 3; q++) {
                float m = logits[map][q][0];
                m = fmaxf(m, logits[map][q][1]);
                m = fmaxf(m, logits[map][q][2]);
                float e0 = __expf(logits[map][q][0] - m);
                float e1 = __expf(logits[map][q][1] - m);
                float e2 = __expf(logits[map][q][2] - m);
                float inv = NORM_FACT / (e0 + e1 + e2);
                p[map][q][0] = e0 * inv;
                p[map][q][1] = e1 * inv;
                p[map][q][2] = e2 * inv;
            }
        }
        float jl[3][3][3];
        #pragma unroll
        for (int map = 0; map < 3; map++)
            #pragma unroll
            for (int q = 0; q < 3; q++)
                #pragma unroll
                for (int o = 0; o < 3; o++)
                    jl[map][q][o] = p[map][q][0] * Wj[o * 3 + 0]
                                  + p[map][q][1] * Wj[o * 3 + 1]
                                  + p[map][q][2] * Wj[o * 3 + 2]
                                  + bj[o];
        #pragma unroll
        for (int q = 0; q < 3; q++) {
            #pragma unroll
            for (int o = 0; o < 3; o++) {
                float accI = 0.0f, accT = 0.0f;
                #pragma unroll
                for (int i = 0; i < 3; i++) {
                    #pragma unroll
                    for (int jx = 0; jx < 3; jx++) {
                        const float w = Wbil[o * 9 + i * 3 + jx];
                        accI += jl[0][q][i] * w * jl[1][q][jx];
                        accT += jl[0][q][i] * w * jl[2][q][jx];
                    }
                }
                attnI[q][o] = accI;
                attnT[q][o] = accT;
            }
        }
    }
    __syncthreads();

    const float* ib = img  + (size_t)b * 3 * D;
    const float* tb = text + (size_t)b * 3 * D;
    float* oi = out + (size_t)(b * 3) * D;
    float* ot = out + (size_t)ROWS * D + (size_t)(b * 3) * D;

    const float ai00 = attnI[0][0], ai01 = attnI[0][1], ai02 = attnI[0][2];
    const float ai10 = attnI[1][0], ai11 = attnI[1][1], ai12 = attnI[1][2];
    const float ai20 = attnI[2][0], ai21 = attnI[2][1], ai22 = attnI[2][2];
    const float at00 = attnT[0][0], at01 = attnT[0][1], at02 = attnT[0][2];
    const float at10 = attnT[1][0], at11 = attnT[1][1], at12 = attnT[1][2];
    const float at20 = attnT[2][0], at21 = attnT[2][1], at22 = attnT[2][2];

    for (int d = tid; d < D; d += 256) {
        const float i0 = ib[d], i1 = ib[D + d], i2 = ib[2 * D + d];
        const float t0 = tb[d], t1 = tb[D + d], t2 = tb[2 * D + d];
        oi[0 * D + d] = ai00 * i0 + ai01 * i1 + ai02 * i2;
        oi[1 * D + d] = ai10 * i0 + ai11 * i1 + ai12 * i2;
        oi[2 * D + d] = ai20 * i0 + ai21 * i1 + ai22 * i2;
        ot[0 * D + d] = at00 * t0 + at01 * t1 + at02 * t2;
        ot[1 * D + d] = at10 * t0 + at11 * t1 + at12 * t2;
        ot[2 * D + d] = at20 * t0 + at21 * t1 + at22 * t2;
    }
}

// ---------------------------------------------------------------------------
extern "C" void kernel_launch(void* const* d_in, const int* in_sizes, int n_in,
                              void* d_out, int out_size)
{
    const float* img  = (const float*)d_in[0];
    const float* text = (const float*)d_in[1];
    const float* Wq   = (const float*)d_in[2];
    const float* bq   = (const float*)d_in[3];
    const float* Wk   = (const float*)d_in[4];
    const float* bk   = (const float*)d_in[5];
    const float* Wj   = (const float*)d_in[6];
    const float* bj   = (const float*)d_in[7];
    const float* Wbil = (const float*)d_in[8];
    float* out = (float*)d_out;

    cudaFuncSetAttribute(gemm_hybrid_kernel,
                         cudaFuncAttributeMaxDynamicSharedMemorySize, SMEM_TOTAL);

    // bf16 hi/lo conversion for tc rows + weights
    {
        const size_t n4a = (size_t)TC_ROWS * GK / 4;       // rows [0, 32768)
        convertA_kernel<<<(unsigned)(n4a / 256), 256>>>(img, text);
        const size_t n4b = (size_t)GN * GK / 4;
        convertB_kernel<<<(unsigned)(n4b / 256), 256>>>(Wq, Wk);
    }
    // k-major fp32 copies for the FFMA path
    {
        dim3 ga(GK / 32, FF_ROWS / 32);
        transA_kernel<<<ga, dim3(32, 8)>>>(text);
        dim3 gb(GK / 32, GN / 32);
        transB_kernel<<<gb, dim3(32, 8)>>>(Wq, Wk);
    }

    dim3 grid(GN / TILE_N, TC_ROWS / TILE_M);   // 16 x 256
    gemm_hybrid_kernel<<<grid, NTHREADS, SMEM_TOTAL>>>(bq, bk);

    attn_epilogue_kernel<<<BATCH, 256>>>(img, text, Wj, bj, Wbil, out);
}

// round 5
// speedup vs baseline: 1.9804x; 1.9804x over previous
#include <cuda_runtime.h>
#include <cuda_bf16.h>
#include <cstdint>

// ---------------------------------------------------------------------------
// Problem constants
// ---------------------------------------------------------------------------
static constexpr int BATCH = 8192;
static constexpr int D     = 2048;           // input feature dim (K of GEMM)
static constexpr int DK    = 1024;           // projection dim
static constexpr int ROWS  = BATCH * 3;      // 24576 rows per tensor
static constexpr int GM    = ROWS * 2;       // 49152 (img rows then text rows)
static constexpr int GN    = 2 * DK;         // 2048  (Q cols then K cols)
static constexpr int GK    = D;              // 2048
static constexpr float NORM_FACT = 0.03125f; // 1/sqrt(1024)

// GEMM tiling
static constexpr int TILE_M = 128;
static constexpr int TILE_N = 128;
static constexpr int BK     = 64;            // bf16 elems per chunk (128B rows)
static constexpr int NCHUNK = GK / BK;       // 32
static constexpr int NSTAGE = 3;

static constexpr int OP_TILE      = 128 * 128;        // one operand tile: 128 rows x 128B
static constexpr int STAGE_BYTES  = 3 * OP_TILE;      // Ah, Bh, Bl = 48KB
static constexpr int SMEM_TOTAL   = NSTAGE * STAGE_BYTES; // 144KB

// ---------------------------------------------------------------------------
// Device scratch
// ---------------------------------------------------------------------------
__device__ __align__(16) __nv_bfloat16 g_Ah[(size_t)GM * GK];
__device__ __align__(16) __nv_bfloat16 g_Bh[(size_t)GN * GK];
__device__ __align__(16) __nv_bfloat16 g_Bl[(size_t)GN * GK];
__device__ __align__(16) float         g_QK[(size_t)GM * GN];

// ---------------------------------------------------------------------------
// PTX helpers (portable sm_80-era ISA: cp.async, ldmatrix, mma.sync)
// ---------------------------------------------------------------------------
__device__ __forceinline__ uint32_t smem_u32(const void* p) {
    uint32_t a;
    asm("{ .reg .u64 t; cvta.to.shared.u64 t, %1; cvt.u32.u64 %0, t; }" : "=r"(a) : "l"(p));
    return a;
}
__device__ __forceinline__ void cp16(uint32_t dst, const void* src) {
    asm volatile("cp.async.cg.shared.global [%0], [%1], 16;" :: "r"(dst), "l"(src));
}
__device__ __forceinline__ void cp_commit() {
    asm volatile("cp.async.commit_group;" ::: "memory");
}
template <int N>
__device__ __forceinline__ void cp_wait() {
    asm volatile("cp.async.wait_group %0;" :: "n"(N) : "memory");
}
__device__ __forceinline__ void ldmx4(uint32_t* r, uint32_t addr) {
    asm volatile("ldmatrix.sync.aligned.m8n8.x4.shared.b16 {%0,%1,%2,%3}, [%4];"
                 : "=r"(r[0]), "=r"(r[1]), "=r"(r[2]), "=r"(r[3]) : "r"(addr));
}
__device__ __forceinline__ void mma_bf16(float* c, const uint32_t* a, uint32_t b0, uint32_t b1) {
    asm volatile(
        "mma.sync.aligned.m16n8k16.row.col.f32.bf16.bf16.f32 "
        "{%0,%1,%2,%3}, {%4,%5,%6,%7}, {%8,%9}, {%0,%1,%2,%3};"
        : "+f"(c[0]), "+f"(c[1]), "+f"(c[2]), "+f"(c[3])
        : "r"(a[0]), "r"(a[1]), "r"(a[2]), "r"(a[3]), "r"(b0), "r"(b1));
}

// ---------------------------------------------------------------------------
// Convert kernels
//   A: fp32 -> single bf16 (hi only)
//   B: fp32 -> bf16 hi + lo residual (17-bit effective)
// ---------------------------------------------------------------------------
__global__ void convertA_kernel(const float* __restrict__ img, const float* __restrict__ text) {
    const size_t i = (size_t)blockIdx.x * blockDim.x + threadIdx.x;     // float4 index
    const size_t half = (size_t)ROWS * GK / 4;
    const float4 v = (i < half) ? ((const float4*)img)[i] : ((const float4*)text)[i - half];
    __nv_bfloat162* ah = (__nv_bfloat162*)g_Ah;
    ah[2 * i]     = __nv_bfloat162(__float2bfloat16_rn(v.x), __float2bfloat16_rn(v.y));
    ah[2 * i + 1] = __nv_bfloat162(__float2bfloat16_rn(v.z), __float2bfloat16_rn(v.w));
}

__global__ void convertB_kernel(const float* __restrict__ Wq, const float* __restrict__ Wk) {
    const size_t i = (size_t)blockIdx.x * blockDim.x + threadIdx.x;     // float4 index
    const size_t half = (size_t)DK * GK / 4;
    const float4 v = (i < half) ? ((const float4*)Wq)[i] : ((const float4*)Wk)[i - half];
    __nv_bfloat16 h0 = __float2bfloat16_rn(v.x), h1 = __float2bfloat16_rn(v.y);
    __nv_bfloat16 h2 = __float2bfloat16_rn(v.z), h3 = __float2bfloat16_rn(v.w);
    __nv_bfloat162* bh = (__nv_bfloat162*)g_Bh;
    __nv_bfloat162* bl = (__nv_bfloat162*)g_Bl;
    bh[2 * i]     = __nv_bfloat162(h0, h1);
    bh[2 * i + 1] = __nv_bfloat162(h2, h3);
    bl[2 * i]     = __nv_bfloat162(__float2bfloat16_rn(v.x - __bfloat162float(h0)),
                                   __float2bfloat16_rn(v.y - __bfloat162float(h1)));
    bl[2 * i + 1] = __nv_bfloat162(__float2bfloat16_rn(v.z - __bfloat162float(h2)),
                                   __float2bfloat16_rn(v.w - __bfloat162float(h3)));
}

// ---------------------------------------------------------------------------
// mma.sync split GEMM: g_QK = A @ B^T + bias
//   2 terms: Ah*Bh + Ah*Bl  (A single bf16, B 17-bit via hi+lo)
// 128x128 CTA tile, 8 warps (2x4), 64x32 warp tile, BK=64, 3-stage cp.async.
// ---------------------------------------------------------------------------
__global__ void __launch_bounds__(256, 1) gemm_mma_kernel(
    const float* __restrict__ bq, const float* __restrict__ bk)
{
    extern __shared__ char smem[];
    const uint32_t sbase = smem_u32(smem);
    const int tid  = threadIdx.x;
    const int warp = tid >> 5;
    const int lane = tid & 31;

    const int bm = blockIdx.y * TILE_M;
    const int bn = blockIdx.x * TILE_N;
    const int wm = warp & 1;     // M half (64 rows)
    const int wn = warp >> 1;    // N quarter (32 cols)

    // ---- load geometry: thread -> (row, 4 consecutive 16B chunks) ----
    const int lr  = tid >> 1;          // 0..127
    const int lc0 = (tid & 1) * 4;     // first 16B chunk (0 or 4) of this row
    const __nv_bfloat16* gAh = g_Ah + (size_t)(bm + lr) * GK + lc0 * 8;
    const __nv_bfloat16* gBh = g_Bh + (size_t)(bn + lr) * GK + lc0 * 8;
    const __nv_bfloat16* gBl = g_Bl + (size_t)(bn + lr) * GK + lc0 * 8;

    uint32_t swoff[4];   // swizzled smem byte offsets for the 4 chunks
    #pragma unroll
    for (int i = 0; i < 4; i++)
        swoff[i] = (uint32_t)(lr * 128 + (((lc0 + i) ^ (lr & 7)) * 16));

    auto load_stage = [&](int c, int s) {
        const uint32_t st = sbase + s * STAGE_BYTES;
        const size_t kof = (size_t)c * BK;   // elems
        #pragma unroll
        for (int i = 0; i < 4; i++) {
            cp16(st +               swoff[i], gAh + kof + i * 8);
            cp16(st +     OP_TILE + swoff[i], gBh + kof + i * 8);
            cp16(st + 2 * OP_TILE + swoff[i], gBl + kof + i * 8);
        }
        cp_commit();
    };

    // ---- prologue: fill all stages ----
    #pragma unroll
    for (int s = 0; s < NSTAGE; s++) load_stage(s, s);

    // ---- per-warp ldmatrix addressing ----
    const int lrow = lane & 15;
    const int lsel = lane >> 4;
    uint32_t swz[4];   // per k-step (k16) swizzled offset for lane
    #pragma unroll
    for (int ks = 0; ks < 4; ks++)
        swz[ks] = (uint32_t)(lrow * 128 + (((ks * 2 + lsel) ^ (lrow & 7)) * 16));

    const uint32_t aWarp = sbase + (uint32_t)(wm * 64) * 128;                // within Ah
    const uint32_t bWarp = sbase + OP_TILE + (uint32_t)(wn * 32) * 128;      // within Bh

    float acc[4][4][4];
    #pragma unroll
    for (int i = 0; i < 4; i++)
        #pragma unroll
        for (int j = 0; j < 4; j++)
            #pragma unroll
            for (int k = 0; k < 4; k++) acc[i][j][k] = 0.0f;

    for (int c = 0; c < NCHUNK; c++) {
        const int s = c % NSTAGE;
        cp_wait<NSTAGE - 1>();
        __syncthreads();

        const uint32_t aS = aWarp + s * STAGE_BYTES;
        const uint32_t bS = bWarp + s * STAGE_BYTES;

        #pragma unroll
        for (int ks = 0; ks < 4; ks++) {
            uint32_t ah[4][4], bh[2][4], bl[2][4];
            #pragma unroll
            for (int mf = 0; mf < 4; mf++)
                ldmx4(ah[mf], aS + mf * 2048 + swz[ks]);
            #pragma unroll
            for (int nf2 = 0; nf2 < 2; nf2++) {
                ldmx4(bh[nf2], bS + nf2 * 2048 + swz[ks]);
                ldmx4(bl[nf2], bS + OP_TILE + nf2 * 2048 + swz[ks]);
            }
            #pragma unroll
            for (int mf = 0; mf < 4; mf++) {
                #pragma unroll
                for (int nf = 0; nf < 4; nf++) {
                    const int nf2 = nf >> 1, sub = nf & 1;
                    mma_bf16(acc[mf][nf], ah[mf], bh[nf2][sub], bh[nf2][sub + 2]); // Ah*Bh
                    mma_bf16(acc[mf][nf], ah[mf], bl[nf2][sub], bl[nf2][sub + 2]); // Ah*Bl
                }
            }
        }

        __syncthreads();   // all warps done reading stage s before overwrite
        if (c + NSTAGE < NCHUNK) load_stage(c + NSTAGE, s);
        else                     cp_commit();   // keep wait_group math valid
    }

    // ---- epilogue: bias + writeback ----
    const int trow = lane >> 2;
    const int tcol = (lane & 3) * 2;
    const bool isQ = (bn < DK);
    const float* bias = isQ ? bq : bk;
    const int bcol0 = isQ ? bn : (bn - DK);

    #pragma unroll
    for (int mf = 0; mf < 4; mf++) {
        const int r0 = bm + wm * 64 + mf * 16 + trow;
        #pragma unroll
        for (int nf = 0; nf < 4; nf++) {
            const int coln = wn * 32 + nf * 8 + tcol;  // within tile
            const float2 bv = *(const float2*)(bias + bcol0 + coln);
            float2 v0, v1;
            v0.x = acc[mf][nf][0] + bv.x;
            v0.y = acc[mf][nf][1] + bv.y;
            v1.x = acc[mf][nf][2] + bv.x;
            v1.y = acc[mf][nf][3] + bv.y;
            *(float2*)&g_QK[(size_t)r0 * GN + bn + coln]       = v0;
            *(float2*)&g_QK[(size_t)(r0 + 8) * GN + bn + coln] = v1;
        }
    }
}

// ---------------------------------------------------------------------------
// Kernel: per-batch attention algebra + output epilogue
// ---------------------------------------------------------------------------
__global__ void __launch_bounds__(256) attn_epilogue_kernel(
    const float* __restrict__ img,
    const float* __restrict__ text,
    const float* __restrict__ Wj,
    const float* __restrict__ bj,
    const float* __restrict__ Wbil,
    float* __restrict__ out)
{
    const int b    = blockIdx.x;
    const int tid  = threadIdx.x;
    const int warp = tid >> 5;
    const int lane = tid & 31;

    __shared__ float logits[3][3][3];
    __shared__ float attnI[3][3];
    __shared__ float attnT[3][3];

    for (int idx = warp; idx < 27; idx += 8) {
        const int map = idx / 9;
        const int r   = idx % 9;
        const int q   = r / 3;
        const int s   = r % 3;

        const size_t mi_q = (size_t)(b * 3 + q) * GN;
        const size_t mi_s = (size_t)(b * 3 + s) * GN;
        const size_t mt_q = (size_t)(ROWS + b * 3 + q) * GN;
        const size_t mt_s = (size_t)(ROWS + b * 3 + s) * GN;

        const float* a;
        const float* v;
        if (map == 0)      { a = g_QK + mi_q; v = g_QK + mt_s + DK; }
        else if (map == 1) { a = g_QK + mi_q; v = g_QK + mi_s + DK; }
        else               { a = g_QK + mt_q; v = g_QK + mt_s + DK; }

        float sum = 0.0f;
        for (int t = lane; t < DK; t += 32)
            sum += a[t] * v[t];
        #pragma unroll
        for (int off = 16; off > 0; off >>= 1)
            sum += __shfl_xor_sync(0xFFFFFFFFu, sum, off);
        if (lane == 0) logits[map][q][s] = sum;
    }
    __syncthreads();

    if (tid == 0) {
        float p[3][3][3];
        #pragma unroll
        for (int map = 0; map < 3; map++) {
            #pragma unroll
            for (int q = 0; q < 3; q++) {
                float m = logits[map][q][0];
                m = fmaxf(m, logits[map][q][1]);
                m = fmaxf(m, logits[map][q][2]);
                float e0 = __expf(logits[map][q][0] - m);
                float e1 = __expf(logits[map][q][1] - m);
                float e2 = __expf(logits[map][q][2] - m);
                float inv = NORM_FACT / (e0 + e1 + e2);
                p[map][q][0] = e0 * inv;
                p[map][q][1] = e1 * inv;
                p[map][q][2] = e2 * inv;
            }
        }
        float jl[3][3][3];
        #pragma unroll
        for (int map = 0; map < 3; map++)
            #pragma unroll
            for (int q = 0; q < 3; q++)
                #pragma unroll
                for (int o = 0; o < 3; o++)
                    jl[map][q][o] = p[map][q][0] * Wj[o * 3 + 0]
                                  + p[map][q][1] * Wj[o * 3 + 1]
                                  + p[map][q][2] * Wj[o * 3 + 2]
                                  + bj[o];
        #pragma unroll
        for (int q = 0; q < 3; q++) {
            #pragma unroll
            for (int o = 0; o < 3; o++) {
                float accI = 0.0f, accT = 0.0f;
                #pragma unroll
                for (int i = 0; i < 3; i++) {
                    #pragma unroll
                    for (int jx = 0; jx < 3; jx++) {
                        const float w = Wbil[o * 9 + i * 3 + jx];
                        accI += jl[0][q][i] * w * jl[1][q][jx];
                        accT += jl[0][q][i] * w * jl[2][q][jx];
                    }
                }
                attnI[q][o] = accI;
                attnT[q][o] = accT;
            }
        }
    }
    __syncthreads();

    const float* ib = img  + (size_t)b * 3 * D;
    const float* tb = text + (size_t)b * 3 * D;
    float* oi = out + (size_t)(b * 3) * D;
    float* ot = out + (size_t)ROWS * D + (size_t)(b * 3) * D;

    const float ai00 = attnI[0][0], ai01 = attnI[0][1], ai02 = attnI[0][2];
    const float ai10 = attnI[1][0], ai11 = attnI[1][1], ai12 = attnI[1][2];
    const float ai20 = attnI[2][0], ai21 = attnI[2][1], ai22 = attnI[2][2];
    const float at00 = attnT[0][0], at01 = attnT[0][1], at02 = attnT[0][2];
    const float at10 = attnT[1][0], at11 = attnT[1][1], at12 = attnT[1][2];
    const float at20 = attnT[2][0], at21 = attnT[2][1], at22 = attnT[2][2];

    for (int d = tid; d < D; d += 256) {
        const float i0 = ib[d], i1 = ib[D + d], i2 = ib[2 * D + d];
        const float t0 = tb[d], t1 = tb[D + d], t2 = tb[2 * D + d];
        oi[0 * D + d] = ai00 * i0 + ai01 * i1 + ai02 * i2;
        oi[1 * D + d] = ai10 * i0 + ai11 * i1 + ai12 * i2;
        oi[2 * D + d] = ai20 * i0 + ai21 * i1 + ai22 * i2;
        ot[0 * D + d] = at00 * t0 + at01 * t1 + at02 * t2;
        ot[1 * D + d] = at10 * t0 + at11 * t1 + at12 * t2;
        ot[2 * D + d] = at20 * t0 + at21 * t1 + at22 * t2;
    }
}

// ---------------------------------------------------------------------------
extern "C" void kernel_launch(void* const* d_in, const int* in_sizes, int n_in,
                              void* d_out, int out_size)
{
    const float* img  = (const float*)d_in[0];
    const float* text = (const float*)d_in[1];
    const float* Wq   = (const float*)d_in[2];
    const float* bq   = (const float*)d_in[3];
    const float* Wk   = (const float*)d_in[4];
    const float* bk   = (const float*)d_in[5];
    const float* Wj   = (const float*)d_in[6];
    const float* bj   = (const float*)d_in[7];
    const float* Wbil = (const float*)d_in[8];
    float* out = (float*)d_out;

    cudaFuncSetAttribute(gemm_mma_kernel,
                         cudaFuncAttributeMaxDynamicSharedMemorySize, SMEM_TOTAL);

    {   // convert inputs: A -> bf16, B -> bf16 hi/lo
        const size_t n4a = (size_t)GM * GK / 4;
        convertA_kernel<<<(unsigned)(n4a / 256), 256>>>(img, text);
        const size_t n4b = (size_t)GN * GK / 4;
        convertB_kernel<<<(unsigned)(n4b / 256), 256>>>(Wq, Wk);
    }

    dim3 grid(GN / TILE_N, GM / TILE_M);   // 16 x 384
    gemm_mma_kernel<<<grid, 256, SMEM_TOTAL>>>(bq, bk);

    attn_epilogue_kernel<<<BATCH, 256>>>(img, text, Wj, bj, Wbil, out);
}

// round 6
// speedup vs baseline: 3.2210x; 1.6264x over previous
#include <cuda_runtime.h>
#include <cuda_fp16.h>
#include <cstdint>

// ---------------------------------------------------------------------------
// Problem constants
// ---------------------------------------------------------------------------
static constexpr int BATCH = 8192;
static constexpr int D     = 2048;           // input feature dim (K of GEMM)
static constexpr int DK    = 1024;           // projection dim
static constexpr int ROWS  = BATCH * 3;      // 24576 rows per tensor
static constexpr int GM    = ROWS * 2;       // 49152 (img rows then text rows)
static constexpr int GN    = 2 * DK;         // 2048  (Q cols then K cols)
static constexpr int GK    = D;              // 2048
static constexpr float NORM_FACT = 0.03125f; // 1/sqrt(1024)

// GEMM tiling
static constexpr int TILE_M = 128;
static constexpr int TILE_N = 128;
static constexpr int BK     = 64;            // fp16 elems per chunk (128B rows)
static constexpr int NCHUNK = GK / BK;       // 32
static constexpr int NSTAGE = 4;

static constexpr int OP_TILE      = 128 * 128;          // one operand tile: 128 rows x 128B
static constexpr int STAGE_BYTES  = 2 * OP_TILE;        // A, B = 32KB
static constexpr int SMEM_TOTAL   = NSTAGE * STAGE_BYTES; // 128KB

// ---------------------------------------------------------------------------
// Device scratch
// ---------------------------------------------------------------------------
__device__ __align__(16) __half g_A[(size_t)GM * GK];
__device__ __align__(16) __half g_B[(size_t)GN * GK];
__device__ __align__(16) __half g_QK[(size_t)GM * GN];

// ---------------------------------------------------------------------------
// PTX helpers (portable sm_80-era ISA: cp.async, ldmatrix, mma.sync)
// ---------------------------------------------------------------------------
__device__ __forceinline__ uint32_t smem_u32(const void* p) {
    uint32_t a;
    asm("{ .reg .u64 t; cvta.to.shared.u64 t, %1; cvt.u32.u64 %0, t; }" : "=r"(a) : "l"(p));
    return a;
}
__device__ __forceinline__ void cp16(uint32_t dst, const void* src) {
    asm volatile("cp.async.cg.shared.global [%0], [%1], 16;" :: "r"(dst), "l"(src));
}
__device__ __forceinline__ void cp_commit() {
    asm volatile("cp.async.commit_group;" ::: "memory");
}
template <int N>
__device__ __forceinline__ void cp_wait() {
    asm volatile("cp.async.wait_group %0;" :: "n"(N) : "memory");
}
__device__ __forceinline__ void ldmx4(uint32_t* r, uint32_t addr) {
    asm volatile("ldmatrix.sync.aligned.m8n8.x4.shared.b16 {%0,%1,%2,%3}, [%4];"
                 : "=r"(r[0]), "=r"(r[1]), "=r"(r[2]), "=r"(r[3]) : "r"(addr));
}
__device__ __forceinline__ void mma_fp16(float* c, const uint32_t* a, uint32_t b0, uint32_t b1) {
    asm volatile(
        "mma.sync.aligned.m16n8k16.row.col.f32.f16.f16.f32 "
        "{%0,%1,%2,%3}, {%4,%5,%6,%7}, {%8,%9}, {%0,%1,%2,%3};"
        : "+f"(c[0]), "+f"(c[1]), "+f"(c[2]), "+f"(c[3])
        : "r"(a[0]), "r"(a[1]), "r"(a[2]), "r"(a[3]), "r"(b0), "r"(b1));
}

// ---------------------------------------------------------------------------
// Convert kernels: fp32 -> single fp16
// ---------------------------------------------------------------------------
__global__ void convertA_kernel(const float* __restrict__ img, const float* __restrict__ text) {
    const size_t i = (size_t)blockIdx.x * blockDim.x + threadIdx.x;     // float4 index
    const size_t half_n = (size_t)ROWS * GK / 4;
    const float4 v = (i < half_n) ? ((const float4*)img)[i] : ((const float4*)text)[i - half_n];
    __half2* a2 = (__half2*)g_A;
    a2[2 * i]     = __floats2half2_rn(v.x, v.y);
    a2[2 * i + 1] = __floats2half2_rn(v.z, v.w);
}

__global__ void convertB_kernel(const float* __restrict__ Wq, const float* __restrict__ Wk) {
    const size_t i = (size_t)blockIdx.x * blockDim.x + threadIdx.x;     // float4 index
    const size_t half_n = (size_t)DK * GK / 4;
    const float4 v = (i < half_n) ? ((const float4*)Wq)[i] : ((const float4*)Wk)[i - half_n];
    __half2* b2 = (__half2*)g_B;
    b2[2 * i]     = __floats2half2_rn(v.x, v.y);
    b2[2 * i + 1] = __floats2half2_rn(v.z, v.w);
}

// ---------------------------------------------------------------------------
// mma.sync fp16 GEMM: g_QK = A @ B^T + bias  (single term, fp32 accumulate)
// 128x128 CTA tile, 8 warps (2x4), 64x32 warp tile, BK=64, 4-stage cp.async.
// ---------------------------------------------------------------------------
__global__ void __launch_bounds__(256, 1) gemm_mma_kernel(
    const float* __restrict__ bq, const float* __restrict__ bk)
{
    extern __shared__ char smem[];
    const uint32_t sbase = smem_u32(smem);
    const int tid  = threadIdx.x;
    const int warp = tid >> 5;
    const int lane = tid & 31;

    const int bm = blockIdx.y * TILE_M;
    const int bn = blockIdx.x * TILE_N;
    const int wm = warp & 1;     // M half (64 rows)
    const int wn = warp >> 1;    // N quarter (32 cols)

    // ---- load geometry: thread -> (row, 4 consecutive 16B chunks) ----
    const int lr  = tid >> 1;          // 0..127
    const int lc0 = (tid & 1) * 4;     // first 16B chunk (0 or 4) of this row
    const __half* gA = g_A + (size_t)(bm + lr) * GK + lc0 * 8;
    const __half* gB = g_B + (size_t)(bn + lr) * GK + lc0 * 8;

    uint32_t swoff[4];   // swizzled smem byte offsets for the 4 chunks
    #pragma unroll
    for (int i = 0; i < 4; i++)
        swoff[i] = (uint32_t)(lr * 128 + (((lc0 + i) ^ (lr & 7)) * 16));

    auto load_stage = [&](int c, int s) {
        const uint32_t st = sbase + s * STAGE_BYTES;
        const size_t kof = (size_t)c * BK;   // elems
        #pragma unroll
        for (int i = 0; i < 4; i++) {
            cp16(st +           swoff[i], gA + kof + i * 8);
            cp16(st + OP_TILE + swoff[i], gB + kof + i * 8);
        }
        cp_commit();
    };

    // ---- prologue: fill all stages ----
    #pragma unroll
    for (int s = 0; s < NSTAGE; s++) load_stage(s, s);

    // ---- per-warp ldmatrix addressing ----
    const int lrow = lane & 15;
    const int lsel = lane >> 4;
    uint32_t swz[4];   // per k-step (k16) swizzled offset for lane
    #pragma unroll
    for (int ks = 0; ks < 4; ks++)
        swz[ks] = (uint32_t)(lrow * 128 + (((ks * 2 + lsel) ^ (lrow & 7)) * 16));

    const uint32_t aWarp = sbase + (uint32_t)(wm * 64) * 128;                // within A
    const uint32_t bWarp = sbase + OP_TILE + (uint32_t)(wn * 32) * 128;      // within B

    float acc[4][4][4];
    #pragma unroll
    for (int i = 0; i < 4; i++)
        #pragma unroll
        for (int j = 0; j < 4; j++)
            #pragma unroll
            for (int k = 0; k < 4; k++) acc[i][j][k] = 0.0f;

    for (int c = 0; c < NCHUNK; c++) {
        const int s = c % NSTAGE;
        cp_wait<NSTAGE - 1>();
        __syncthreads();

        const uint32_t aS = aWarp + s * STAGE_BYTES;
        const uint32_t bS = bWarp + s * STAGE_BYTES;

        #pragma unroll
        for (int ks = 0; ks < 4; ks++) {
            uint32_t ah[4][4], bh[2][4];
            #pragma unroll
            for (int mf = 0; mf < 4; mf++)
                ldmx4(ah[mf], aS + mf * 2048 + swz[ks]);
            #pragma unroll
            for (int nf2 = 0; nf2 < 2; nf2++)
                ldmx4(bh[nf2], bS + nf2 * 2048 + swz[ks]);
            #pragma unroll
            for (int mf = 0; mf < 4; mf++) {
                #pragma unroll
                for (int nf = 0; nf < 4; nf++) {
                    const int nf2 = nf >> 1, sub = nf & 1;
                    mma_fp16(acc[mf][nf], ah[mf], bh[nf2][sub], bh[nf2][sub + 2]);
                }
            }
        }

        __syncthreads();   // all warps done reading stage s before overwrite
        if (c + NSTAGE < NCHUNK) load_stage(c + NSTAGE, s);
        else                     cp_commit();   // keep wait_group math valid
    }

    // ---- epilogue: bias + writeback (fp16) ----
    const int trow = lane >> 2;
    const int tcol = (lane & 3) * 2;
    const bool isQ = (bn < DK);
    const float* bias = isQ ? bq : bk;
    const int bcol0 = isQ ? bn : (bn - DK);

    #pragma unroll
    for (int mf = 0; mf < 4; mf++) {
        const int r0 = bm + wm * 64 + mf * 16 + trow;
        #pragma unroll
        for (int nf = 0; nf < 4; nf++) {
            const int coln = wn * 32 + nf * 8 + tcol;  // within tile
            const float2 bv = *(const float2*)(bias + bcol0 + coln);
            __half2 v0 = __floats2half2_rn(acc[mf][nf][0] + bv.x, acc[mf][nf][1] + bv.y);
            __half2 v1 = __floats2half2_rn(acc[mf][nf][2] + bv.x, acc[mf][nf][3] + bv.y);
            *(__half2*)&g_QK[(size_t)r0 * GN + bn + coln]       = v0;
            *(__half2*)&g_QK[(size_t)(r0 + 8) * GN + bn + coln] = v1;
        }
    }
}

// ---------------------------------------------------------------------------
// Kernel: per-batch attention algebra + output epilogue (QK now fp16)
// ---------------------------------------------------------------------------
__global__ void __launch_bounds__(256) attn_epilogue_kernel(
    const float* __restrict__ img,
    const float* __restrict__ text,
    const float* __restrict__ Wj,
    const float* __restrict__ bj,
    const float* __restrict__ Wbil,
    float* __restrict__ out)
{
    const int b    = blockIdx.x;
    const int tid  = threadIdx.x;
    const int warp = tid >> 5;
    const int lane = tid & 31;

    __shared__ float logits[3][3][3];
    __shared__ float attnI[3][3];
    __shared__ float attnT[3][3];

    for (int idx = warp; idx < 27; idx += 8) {
        const int map = idx / 9;
        const int r   = idx % 9;
        const int q   = r / 3;
        const int s   = r % 3;

        const size_t mi_q = (size_t)(b * 3 + q) * GN;
        const size_t mi_s = (size_t)(b * 3 + s) * GN;
        const size_t mt_q = (size_t)(ROWS + b * 3 + q) * GN;
        const size_t mt_s = (size_t)(ROWS + b * 3 + s) * GN;

        const __half* a;
        const __half* v;
        if (map == 0)      { a = g_QK + mi_q; v = g_QK + mt_s + DK; }
        else if (map == 1) { a = g_QK + mi_q; v = g_QK + mi_s + DK; }
        else               { a = g_QK + mt_q; v = g_QK + mt_s + DK; }

        const __half2* a2 = (const __half2*)a;
        const __half2* v2 = (const __half2*)v;
        float sum = 0.0f;
        for (int t = lane; t < DK / 2; t += 32) {
            const float2 af = __half22float2(a2[t]);
            const float2 vf = __half22float2(v2[t]);
            sum += af.x * vf.x + af.y * vf.y;
        }
        #pragma unroll
        for (int off = 16; off > 0; off >>= 1)
            sum += __shfl_xor_sync(0xFFFFFFFFu, sum, off);
        if (lane == 0) logits[map][q][s] = sum;
    }
    __syncthreads();

    if (tid == 0) {
        float p[3][3][3];
        #pragma unroll
        for (int map = 0; map < 3; map++) {
            #pragma unroll
            for (int q = 0; q < 3; q++) {
                float m = logits[map][q][0];
                m = fmaxf(m, logits[map][q][1]);
                m = fmaxf(m, logits[map][q][2]);
                float e0 = __expf(logits[map][q][0] - m);
                float e1 = __expf(logits[map][q][1] - m);
                float e2 = __expf(logits[map][q][2] - m);
                float inv = NORM_FACT / (e0 + e1 + e2);
                p[map][q][0] = e0 * inv;
                p[map][q][1] = e1 * inv;
                p[map][q][2] = e2 * inv;
            }
        }
        float jl[3][3][3];
        #pragma unroll
        for (int map = 0; map < 3; map++)
            #pragma unroll
            for (int q = 0; q < 3; q++)
                #pragma unroll
                for (int o = 0; o < 3; o++)
                    jl[map][q][o] = p[map][q][0] * Wj[o * 3 + 0]
                                  + p[map][q][1] * Wj[o * 3 + 1]
                                  + p[map][q][2] * Wj[o * 3 + 2]
                                  + bj[o];
        #pragma unroll
        for (int q = 0; q < 3; q++) {
            #pragma unroll
            for (int o = 0; o < 3; o++) {
                float accI = 0.0f, accT = 0.0f;
                #pragma unroll
                for (int i = 0; i < 3; i++) {
                    #pragma unroll
                    for (int jx = 0; jx < 3; jx++) {
                        const float w = Wbil[o * 9 + i * 3 + jx];
                        accI += jl[0][q][i] * w * jl[1][q][jx];
                        accT += jl[0][q][i] * w * jl[2][q][jx];
                    }
                }
                attnI[q][o] = accI;
                attnT[q][o] = accT;
            }
        }
    }
    __syncthreads();

    const float* ib = img  + (size_t)b * 3 * D;
    const float* tb = text + (size_t)b * 3 * D;
    float* oi = out + (size_t)(b * 3) * D;
    float* ot = out + (size_t)ROWS * D + (size_t)(b * 3) * D;

    const float ai00 = attnI[0][0], ai01 = attnI[0][1], ai02 = attnI[0][2];
    const float ai10 = attnI[1][0], ai11 = attnI[1][1], ai12 = attnI[1][2];
    const float ai20 = attnI[2][0], ai21 = attnI[2][1], ai22 = attnI[2][2];
    const float at00 = attnT[0][0], at01 = attnT[0][1], at02 = attnT[0][2];
    const float at10 = attnT[1][0], at11 = attnT[1][1], at12 = attnT[1][2];
    const float at20 = attnT[2][0], at21 = attnT[2][1], at22 = attnT[2][2];

    for (int d = tid; d < D; d += 256) {
        const float i0 = ib[d], i1 = ib[D + d], i2 = ib[2 * D + d];
        const float t0 = tb[d], t1 = tb[D + d], t2 = tb[2 * D + d];
        oi[0 * D + d] = ai00 * i0 + ai01 * i1 + ai02 * i2;
        oi[1 * D + d] = ai10 * i0 + ai11 * i1 + ai12 * i2;
        oi[2 * D + d] = ai20 * i0 + ai21 * i1 + ai22 * i2;
        ot[0 * D + d] = at00 * t0 + at01 * t1 + at02 * t2;
        ot[1 * D + d] = at10 * t0 + at11 * t1 + at12 * t2;
        ot[2 * D + d] = at20 * t0 + at21 * t1 + at22 * t2;
    }
}

// ---------------------------------------------------------------------------
extern "C" void kernel_launch(void* const* d_in, const int* in_sizes, int n_in,
                              void* d_out, int out_size)
{
    const float* img  = (const float*)d_in[0];
    const float* text = (const float*)d_in[1];
    const float* Wq   = (const float*)d_in[2];
    const float* bq   = (const float*)d_in[3];
    const float* Wk   = (const float*)d_in[4];
    const float* bk   = (const float*)d_in[5];
    const float* Wj   = (const float*)d_in[6];
    const float* bj   = (const float*)d_in[7];
    const float* Wbil = (const float*)d_in[8];
    float* out = (float*)d_out;

    cudaFuncSetAttribute(gemm_mma_kernel,
                         cudaFuncAttributeMaxDynamicSharedMemorySize, SMEM_TOTAL);

    {   // convert inputs to fp16
        const size_t n4a = (size_t)GM * GK / 4;
        convertA_kernel<<<(unsigned)(n4a / 256), 256>>>(img, text);
        const size_t n4b = (size_t)GN * GK / 4;
        convertB_kernel<<<(unsigned)(n4b / 256), 256>>>(Wq, Wk);
    }

    dim3 grid(GN / TILE_N, GM / TILE_M);   // 16 x 384
    gemm_mma_kernel<<<grid, 256, SMEM_TOTAL>>>(bq, bk);

    attn_epilogue_kernel<<<BATCH, 256>>>(img, text, Wj, bj, Wbil, out);
}

// round 7
// speedup vs baseline: 3.6946x; 1.1470x over previous
#include <cuda_runtime.h>
#include <cuda_fp16.h>
#include <cstdint>

// ---------------------------------------------------------------------------
// Problem constants
// ---------------------------------------------------------------------------
static constexpr int BATCH = 8192;
static constexpr int D     = 2048;           // input feature dim (K of GEMM)
static constexpr int DK    = 1024;           // projection dim
static constexpr int ROWS  = BATCH * 3;      // 24576 rows per tensor
static constexpr int GM    = ROWS * 2;       // 49152 (img rows then text rows)
static constexpr int GN    = 2 * DK;         // 2048  (Q cols then K cols)
static constexpr int GK    = D;              // 2048
static constexpr float NORM_FACT = 0.03125f; // 1/sqrt(1024)

// GEMM tiling
static constexpr int TILE_M = 128;
static constexpr int TILE_N = 256;
static constexpr int BK     = 64;            // fp16 elems per chunk (128B rows)
static constexpr int NCHUNK = GK / BK;       // 32
static constexpr int NSTAGE = 4;

static constexpr int A_TILE = TILE_M * 128;             // 16 KB
static constexpr int B_TILE = TILE_N * 128;             // 32 KB
static constexpr int STAGE_BYTES = A_TILE + B_TILE;     // 48 KB
static constexpr int SMEM_TOTAL  = NSTAGE * STAGE_BYTES; // 192 KB

// ---------------------------------------------------------------------------
// Device scratch
// ---------------------------------------------------------------------------
__device__ __align__(16) __half g_A[(size_t)GM * GK];
__device__ __align__(16) __half g_B[(size_t)GN * GK];
__device__ __align__(16) __half g_QK[(size_t)GM * GN];

// ---------------------------------------------------------------------------
// PTX helpers (portable sm_80-era ISA: cp.async, ldmatrix, mma.sync)
// ---------------------------------------------------------------------------
__device__ __forceinline__ uint32_t smem_u32(const void* p) {
    uint32_t a;
    asm("{ .reg .u64 t; cvta.to.shared.u64 t, %1; cvt.u32.u64 %0, t; }" : "=r"(a) : "l"(p));
    return a;
}
__device__ __forceinline__ void cp16(uint32_t dst, const void* src) {
    asm volatile("cp.async.cg.shared.global [%0], [%1], 16;" :: "r"(dst), "l"(src));
}
__device__ __forceinline__ void cp_commit() {
    asm volatile("cp.async.commit_group;" ::: "memory");
}
template <int N>
__device__ __forceinline__ void cp_wait() {
    asm volatile("cp.async.wait_group %0;" :: "n"(N) : "memory");
}
__device__ __forceinline__ void ldmx4(uint32_t* r, uint32_t addr) {
    asm volatile("ldmatrix.sync.aligned.m8n8.x4.shared.b16 {%0,%1,%2,%3}, [%4];"
                 : "=r"(r[0]), "=r"(r[1]), "=r"(r[2]), "=r"(r[3]) : "r"(addr));
}
__device__ __forceinline__ void mma_fp16(float* c, const uint32_t* a, uint32_t b0, uint32_t b1) {
    asm volatile(
        "mma.sync.aligned.m16n8k16.row.col.f32.f16.f16.f32 "
        "{%0,%1,%2,%3}, {%4,%5,%6,%7}, {%8,%9}, {%0,%1,%2,%3};"
        : "+f"(c[0]), "+f"(c[1]), "+f"(c[2]), "+f"(c[3])
        : "r"(a[0]), "r"(a[1]), "r"(a[2]), "r"(a[3]), "r"(b0), "r"(b1));
}

// ---------------------------------------------------------------------------
// Convert kernels: fp32 -> single fp16
// ---------------------------------------------------------------------------
__global__ void convertA_kernel(const float* __restrict__ img, const float* __restrict__ text) {
    const size_t i = (size_t)blockIdx.x * blockDim.x + threadIdx.x;     // float4 index
    const size_t half_n = (size_t)ROWS * GK / 4;
    const float4 v = (i < half_n) ? ((const float4*)img)[i] : ((const float4*)text)[i - half_n];
    __half2* a2 = (__half2*)g_A;
    a2[2 * i]     = __floats2half2_rn(v.x, v.y);
    a2[2 * i + 1] = __floats2half2_rn(v.z, v.w);
}

__global__ void convertB_kernel(const float* __restrict__ Wq, const float* __restrict__ Wk) {
    const size_t i = (size_t)blockIdx.x * blockDim.x + threadIdx.x;     // float4 index
    const size_t half_n = (size_t)DK * GK / 4;
    const float4 v = (i < half_n) ? ((const float4*)Wq)[i] : ((const float4*)Wk)[i - half_n];
    __half2* b2 = (__half2*)g_B;
    b2[2 * i]     = __floats2half2_rn(v.x, v.y);
    b2[2 * i + 1] = __floats2half2_rn(v.z, v.w);
}

// ---------------------------------------------------------------------------
// mma.sync fp16 GEMM: g_QK = A @ B^T + bias
// 128x256 CTA tile, 8 warps (2x4), 64x64 warp tile, BK=64, 4-stage cp.async.
// ---------------------------------------------------------------------------
__global__ void __launch_bounds__(256, 1) gemm_mma_kernel(
    const float* __restrict__ bq, const float* __restrict__ bk)
{
    extern __shared__ char smem[];
    const uint32_t sbase = smem_u32(smem);
    const int tid  = threadIdx.x;
    const int warp = tid >> 5;
    const int lane = tid & 31;

    const int bm = blockIdx.y * TILE_M;
    const int bn = blockIdx.x * TILE_N;
    const int wm = warp & 1;     // M half (64 rows)
    const int wn = warp >> 1;    // N quarter (64 cols)

    // ---- load geometry ----
    // A: 128 rows x 4 16B-units -> thread (tid>>1, (tid&1)*4 + i), i<4
    // B: 256 rows x 8 16B-units -> rows tid>>1 and 128+(tid>>1)
    const int lr  = tid >> 1;          // 0..127
    const int lc0 = (tid & 1) * 4;     // first 16B chunk (0 or 4) of this row
    const __half* gA  = g_A + (size_t)(bm + lr) * GK + lc0 * 8;
    const __half* gB0 = g_B + (size_t)(bn + lr) * GK + lc0 * 8;
    const __half* gB1 = g_B + (size_t)(bn + 128 + lr) * GK + lc0 * 8;

    uint32_t swoff[4];   // swizzled smem byte offsets (row lr, chunks lc0..lc0+3)
    #pragma unroll
    for (int i = 0; i < 4; i++)
        swoff[i] = (uint32_t)(lr * 128 + (((lc0 + i) ^ (lr & 7)) * 16));

    auto load_stage = [&](int c, int s) {
        const uint32_t st = sbase + s * STAGE_BYTES;
        const size_t kof = (size_t)c * BK;   // elems
        #pragma unroll
        for (int i = 0; i < 4; i++) {
            cp16(st +                        swoff[i], gA  + kof + i * 8);
            cp16(st + A_TILE +               swoff[i], gB0 + kof + i * 8);
            cp16(st + A_TILE + 128 * 128 +   swoff[i], gB1 + kof + i * 8);
        }
        cp_commit();
    };

    // ---- prologue: fill all stages ----
    #pragma unroll
    for (int s = 0; s < NSTAGE; s++) load_stage(s, s);

    // ---- per-warp ldmatrix addressing ----
    const int lrow = lane & 15;
    const int lsel = lane >> 4;
    uint32_t swz[4];   // per k-step (k16) swizzled offset for lane
    #pragma unroll
    for (int ks = 0; ks < 4; ks++)
        swz[ks] = (uint32_t)(lrow * 128 + (((ks * 2 + lsel) ^ (lrow & 7)) * 16));

    const uint32_t aWarp = sbase + (uint32_t)(wm * 64) * 128;            // within A
    const uint32_t bWarp = sbase + A_TILE + (uint32_t)(wn * 64) * 128;   // within B

    float acc[4][8][4];
    #pragma unroll
    for (int i = 0; i < 4; i++)
        #pragma unroll
        for (int j = 0; j < 8; j++)
            #pragma unroll
            for (int k = 0; k < 4; k++) acc[i][j][k] = 0.0f;

    for (int c = 0; c < NCHUNK; c++) {
        const int s = c % NSTAGE;
        cp_wait<NSTAGE - 1>();
        __syncthreads();

        const uint32_t aS = aWarp + s * STAGE_BYTES;
        const uint32_t bS = bWarp + s * STAGE_BYTES;

        #pragma unroll
        for (int ks = 0; ks < 4; ks++) {
            uint32_t ah[4][4], bh[4][4];
            #pragma unroll
            for (int mf = 0; mf < 4; mf++)
                ldmx4(ah[mf], aS + mf * 2048 + swz[ks]);
            #pragma unroll
            for (int nf2 = 0; nf2 < 4; nf2++)
                ldmx4(bh[nf2], bS + nf2 * 2048 + swz[ks]);
            #pragma unroll
            for (int mf = 0; mf < 4; mf++) {
                #pragma unroll
                for (int nf = 0; nf < 8; nf++) {
                    const int nf2 = nf >> 1, sub = nf & 1;
                    mma_fp16(acc[mf][nf], ah[mf], bh[nf2][sub], bh[nf2][sub + 2]);
                }
            }
        }

        __syncthreads();   // all warps done reading stage s before overwrite
        if (c + NSTAGE < NCHUNK) load_stage(c + NSTAGE, s);
        else                     cp_commit();   // keep wait_group math valid
    }

    // ---- epilogue: bias + writeback (fp16) ----
    const int trow = lane >> 2;
    const int tcol = (lane & 3) * 2;
    const bool isQ = (bn < DK);     // TILE_N=256 aligns with DK split (bn in {0..1792 step 256})
    const float* bias = isQ ? bq : bk;
    const int bcol0 = isQ ? bn : (bn - DK);

    #pragma unroll
    for (int mf = 0; mf < 4; mf++) {
        const int r0 = bm + wm * 64 + mf * 16 + trow;
        #pragma unroll
        for (int nf = 0; nf < 8; nf++) {
            const int coln = wn * 64 + nf * 8 + tcol;  // within tile
            const float2 bv = *(const float2*)(bias + bcol0 + coln);
            __half2 v0 = __floats2half2_rn(acc[mf][nf][0] + bv.x, acc[mf][nf][1] + bv.y);
            __half2 v1 = __floats2half2_rn(acc[mf][nf][2] + bv.x, acc[mf][nf][3] + bv.y);
            *(__half2*)&g_QK[(size_t)r0 * GN + bn + coln]       = v0;
            *(__half2*)&g_QK[(size_t)(r0 + 8) * GN + bn + coln] = v1;
        }
    }
}

// ---------------------------------------------------------------------------
// Kernel: per-batch attention algebra + output epilogue (vectorized)
// ---------------------------------------------------------------------------
__global__ void __launch_bounds__(256) attn_epilogue_kernel(
    const float* __restrict__ img,
    const float* __restrict__ text,
    const float* __restrict__ Wj,
    const float* __restrict__ bj,
    const float* __restrict__ Wbil,
    float* __restrict__ out)
{
    const int b    = blockIdx.x;
    const int tid  = threadIdx.x;
    const int warp = tid >> 5;
    const int lane = tid & 31;

    __shared__ float logits[3][3][3];
    __shared__ float attnI[3][3];
    __shared__ float attnT[3][3];

    for (int idx = warp; idx < 27; idx += 8) {
        const int map = idx / 9;
        const int r   = idx % 9;
        const int q   = r / 3;
        const int s   = r % 3;

        const size_t mi_q = (size_t)(b * 3 + q) * GN;
        const size_t mi_s = (size_t)(b * 3 + s) * GN;
        const size_t mt_q = (size_t)(ROWS + b * 3 + q) * GN;
        const size_t mt_s = (size_t)(ROWS + b * 3 + s) * GN;

        const __half* a;
        const __half* v;
        if (map == 0)      { a = g_QK + mi_q; v = g_QK + mt_s + DK; }
        else if (map == 1) { a = g_QK + mi_q; v = g_QK + mi_s + DK; }
        else               { a = g_QK + mt_q; v = g_QK + mt_s + DK; }

        // 8-wide fp16 loads (uint4 = 8 halves); DK/8 = 128 vectors
        const uint4* a8 = (const uint4*)a;
        const uint4* v8 = (const uint4*)v;
        float sum = 0.0f;
        #pragma unroll
        for (int t = 0; t < 4; t++) {
            const uint4 av = a8[lane + 32 * t];
            const uint4 vv = v8[lane + 32 * t];
            const __half2* ah = (const __half2*)&av;
            const __half2* vh = (const __half2*)&vv;
            #pragma unroll
            for (int u = 0; u < 4; u++) {
                const float2 af = __half22float2(ah[u]);
                const float2 vf = __half22float2(vh[u]);
                sum += af.x * vf.x + af.y * vf.y;
            }
        }
        #pragma unroll
        for (int off = 16; off > 0; off >>= 1)
            sum += __shfl_xor_sync(0xFFFFFFFFu, sum, off);
        if (lane == 0) logits[map][q][s] = sum;
    }
    __syncthreads();

    if (tid == 0) {
        float p[3][3][3];
        #pragma unroll
        for (int map = 0; map < 3; map++) {
            #pragma unroll
            for (int q = 0; q < 3; q++) {
                float m = logits[map][q][0];
                m = fmaxf(m, logits[map][q][1]);
                m = fmaxf(m, logits[map][q][2]);
                float e0 = __expf(logits[map][q][0] - m);
                float e1 = __expf(logits[map][q][1] - m);
                float e2 = __expf(logits[map][q][2] - m);
                float inv = NORM_FACT / (e0 + e1 + e2);
                p[map][q][0] = e0 * inv;
                p[map][q][1] = e1 * inv;
                p[map][q][2] = e2 * inv;
            }
        }
        float jl[3][3][3];
        #pragma unroll
        for (int map = 0; map < 3; map++)
            #pragma unroll
            for (int q = 0; q < 3; q++)
                #pragma unroll
                for (int o = 0; o < 3; o++)
                    jl[map][q][o] = p[map][q][0] * Wj[o * 3 + 0]
                                  + p[map][q][1] * Wj[o * 3 + 1]
                                  + p[map][q][2] * Wj[o * 3 + 2]
                                  + bj[o];
        #pragma unroll
        for (int q = 0; q < 3; q++) {
            #pragma unroll
            for (int o = 0; o < 3; o++) {
                float accI = 0.0f, accT = 0.0f;
                #pragma unroll
                for (int i = 0; i < 3; i++) {
                    #pragma unroll
                    for (int jx = 0; jx < 3; jx++) {
                        const float w = Wbil[o * 9 + i * 3 + jx];
                        accI += jl[0][q][i] * w * jl[1][q][jx];
                        accT += jl[0][q][i] * w * jl[2][q][jx];
                    }
                }
                attnI[q][o] = accI;
                attnT[q][o] = accT;
            }
        }
    }
    __syncthreads();

    // vectorized output epilogue: float4 over D (512 vec4s, 2 iters of 256 threads)
    const float4* ib = (const float4*)(img  + (size_t)b * 3 * D);
    const float4* tb = (const float4*)(text + (size_t)b * 3 * D);
    float4* oi = (float4*)(out + (size_t)(b * 3) * D);
    float4* ot = (float4*)(out + (size_t)ROWS * D + (size_t)(b * 3) * D);
    const int D4 = D / 4;

    const float ai00 = attnI[0][0], ai01 = attnI[0][1], ai02 = attnI[0][2];
    const float ai10 = attnI[1][0], ai11 = attnI[1][1], ai12 = attnI[1][2];
    const float ai20 = attnI[2][0], ai21 = attnI[2][1], ai22 = attnI[2][2];
    const float at00 = attnT[0][0], at01 = attnT[0][1], at02 = attnT[0][2];
    const float at10 = attnT[1][0], at11 = attnT[1][1], at12 = attnT[1][2];
    const float at20 = attnT[2][0], at21 = attnT[2][1], at22 = attnT[2][2];

    #pragma unroll
    for (int it = 0; it < 2; it++) {
        const int d = tid + it * 256;
        const float4 i0 = ib[d], i1 = ib[D4 + d], i2 = ib[2 * D4 + d];
        const float4 t0 = tb[d], t1 = tb[D4 + d], t2 = tb[2 * D4 + d];
        float4 r;
        r.x = ai00 * i0.x + ai01 * i1.x + ai02 * i2.x;
        r.y = ai00 * i0.y + ai01 * i1.y + ai02 * i2.y;
        r.z = ai00 * i0.z + ai01 * i1.z + ai02 * i2.z;
        r.w = ai00 * i0.w + ai01 * i1.w + ai02 * i2.w;
        oi[d] = r;
        r.x = ai10 * i0.x + ai11 * i1.x + ai12 * i2.x;
        r.y = ai10 * i0.y + ai11 * i1.y + ai12 * i2.y;
        r.z = ai10 * i0.z + ai11 * i1.z + ai12 * i2.z;
        r.w = ai10 * i0.w + ai11 * i1.w + ai12 * i2.w;
        oi[D4 + d] = r;
        r.x = ai20 * i0.x + ai21 * i1.x + ai22 * i2.x;
        r.y = ai20 * i0.y + ai21 * i1.y + ai22 * i2.y;
        r.z = ai20 * i0.z + ai21 * i1.z + ai22 * i2.z;
        r.w = ai20 * i0.w + ai21 * i1.w + ai22 * i2.w;
        oi[2 * D4 + d] = r;
        r.x = at00 * t0.x + at01 * t1.x + at02 * t2.x;
        r.y = at00 * t0.y + at01 * t1.y + at02 * t2.y;
        r.z = at00 * t0.z + at01 * t1.z + at02 * t2.z;
        r.w = at00 * t0.w + at01 * t1.w + at02 * t2.w;
        ot[d] = r;
        r.x = at10 * t0.x + at11 * t1.x + at12 * t2.x;
        r.y = at10 * t0.y + at11 * t1.y + at12 * t2.y;
        r.z = at10 * t0.z + at11 * t1.z + at12 * t2.z;
        r.w = at10 * t0.w + at11 * t1.w + at12 * t2.w;
        ot[D4 + d] = r;
        r.x = at20 * t0.x + at21 * t1.x + at22 * t2.x;
        r.y = at20 * t0.y + at21 * t1.y + at22 * t2.y;
        r.z = at20 * t0.z + at21 * t1.z + at22 * t2.z;
        r.w = at20 * t0.w + at21 * t1.w + at22 * t2.w;
        ot[2 * D4 + d] = r;
    }
}

// ---------------------------------------------------------------------------
extern "C" void kernel_launch(void* const* d_in, const int* in_sizes, int n_in,
                              void* d_out, int out_size)
{
    const float* img  = (const float*)d_in[0];
    const float* text = (const float*)d_in[1];
    const float* Wq   = (const float*)d_in[2];
    const float* bq   = (const float*)d_in[3];
    const float* Wk   = (const float*)d_in[4];
    const float* bk   = (const float*)d_in[5];
    const float* Wj   = (const float*)d_in[6];
    const float* bj   = (const float*)d_in[7];
    const float* Wbil = (const float*)d_in[8];
    float* out = (float*)d_out;

    cudaFuncSetAttribute(gemm_mma_kernel,
                         cudaFuncAttributeMaxDynamicSharedMemorySize, SMEM_TOTAL);

    {   // convert inputs to fp16
        const size_t n4a = (size_t)GM * GK / 4;
        convertA_kernel<<<(unsigned)(n4a / 256), 256>>>(img, text);
        const size_t n4b = (size_t)GN * GK / 4;
        convertB_kernel<<<(unsigned)(n4b / 256), 256>>>(Wq, Wk);
    }

    dim3 grid(GN / TILE_N, GM / TILE_M);   // 8 x 384
    gemm_mma_kernel<<<grid, 256, SMEM_TOTAL>>>(bq, bk);

    attn_epilogue_kernel<<<BATCH, 256>>>(img, text, Wj, bj, Wbil, out);
}